// round 15
// baseline (speedup 1.0000x reference)
#include <cuda_runtime.h>
#include <cstdint>

#define B_ 8
#define H_ 1024
#define W_ 1024
#define HW_ (H_*W_)
#define K_ 2048
#define SURV_ 4096
#define NBIN_ 2048
#define NBUCK_ 128
#define CAPB_ 8192
#define NCELL_ 1024   /* 32x32 grid */
#define CELL_INV (1.0f/256.0f)
#define EMAX_ 512
#define RPB_ 16       /* rows per block in k_cand */
#define SBUF_ 2048    /* per-block candidate staging */
#define SPAN_ 3072    /* rank shared staging capacity */
#define PBLK_ 16      /* post blocks per batch */

// ---------------- scratch (static device memory only) ----------------
__device__ unsigned long long g_bcand[B_][NBUCK_][CAPB_];  // bucketed candidates
__device__ unsigned g_bcnt[B_][NBUCK_];                    // zeroed by k_post each call
__device__ unsigned g_base[B_][NBIN_];
__device__ unsigned g_segend[B_][NBIN_];
__device__ unsigned long long g_surv[B_][SURV_];
__device__ int g_m[B_];
__device__ unsigned long long g_topk[B_][K_];
__device__ float4 g_box[B_][K_];
__device__ unsigned g_cellcnt[B_][NCELL_];
__device__ unsigned short g_cellof[B_][K_];
__device__ unsigned short g_cstart[B_][NCELL_ + 1];
__device__ unsigned short g_list[B_][K_];
__device__ unsigned g_edges[B_][EMAX_];
__device__ int g_ne[B_];
__device__ unsigned g_barcnt[B_];   // barrier arrive counters (self-resetting)
__device__ unsigned g_bargen[B_];   // barrier generations (monotone)

// ---------------- K1: local-max candidates (paired separable max9, bucketed emit) ----------------
// block = 16 image rows (256 threads x 4 px), grid = (H/16, B)
__global__ void __launch_bounds__(256) k_cand(const float* __restrict__ sc) {
    const int b = blockIdx.y, h0 = blockIdx.x * RPB_;
    const int tid = threadIdx.x;
    const int w0 = tid * 4;
    const int lane = tid & 31;
    const float NI = -__int_as_float(0x7f800000); // -inf

    __shared__ int scnt;
    __shared__ unsigned long long sbuf[SBUF_];
    __shared__ unsigned scntb[NBUCK_];
    __shared__ unsigned sbase[NBUCK_];
    __shared__ unsigned scur[NBUCK_];
    if (tid < NBUCK_) { scntb[tid] = 0u; scur[tid] = 0u; }
    if (tid == 0) scnt = 0;
    __syncthreads();

    float v[6];
    float h3m[4], h3c[4], h3n[4], h3n2[4];
    float cenc[4], cenn[4], cenn2[4];

    #define LOADROW(hh) do {                                                \
        int _h = (hh);                                                      \
        if ((unsigned)_h >= (unsigned)H_) {                                 \
            v[0]=NI; v[1]=NI; v[2]=NI; v[3]=NI; v[4]=NI; v[5]=NI;           \
        } else {                                                            \
            const float* _r = sc + ((size_t)b * H_ + _h) * W_;              \
            float4 _m = *reinterpret_cast<const float4*>(_r + w0);          \
            float _lw = __shfl_up_sync(0xffffffffu, _m.w, 1);               \
            float _rx = __shfl_down_sync(0xffffffffu, _m.x, 1);             \
            v[1]=_m.x; v[2]=_m.y; v[3]=_m.z; v[4]=_m.w;                     \
            v[0] = lane        ? _lw : ((w0 > 0)      ? _r[w0-1] : NI);     \
            v[5] = (lane != 31)? _rx : ((w0 + 4 < W_) ? _r[w0+4] : NI);     \
        }                                                                   \
    } while (0)
    #define H3(d) do {                                                      \
        float _q0 = fmaxf(v[0], v[1]);                                      \
        float _q2 = fmaxf(v[2], v[3]);                                      \
        float _q4 = fmaxf(v[4], v[5]);                                      \
        d[0] = fmaxf(_q0, v[2]);                                            \
        d[1] = fmaxf(v[1], _q2);                                            \
        d[2] = fmaxf(_q2, v[4]);                                            \
        d[3] = fmaxf(v[3], _q4);                                            \
    } while (0)
    #define EMIT(s_, hh_, p_) do {                                          \
        int _pos = atomicAdd(&scnt, 1);                                     \
        if (_pos < SBUF_) {                                                 \
            unsigned _idx = (unsigned)((hh_) * W_ + w0 + (p_));             \
            unsigned _sb = __float_as_uint(s_);                             \
            sbuf[_pos] = ((unsigned long long)_sb << 32) | (unsigned)(~_idx);\
        }                                                                   \
    } while (0)

    LOADROW(h0 - 1); H3(h3m);
    LOADROW(h0);     H3(h3c); cenc[0]=v[1]; cenc[1]=v[2]; cenc[2]=v[3]; cenc[3]=v[4];

    #pragma unroll
    for (int r = 0; r < RPB_; r += 2) {
        LOADROW(h0 + r + 1); H3(h3n);  cenn[0]=v[1];  cenn[1]=v[2];  cenn[2]=v[3];  cenn[3]=v[4];
        LOADROW(h0 + r + 2); H3(h3n2); cenn2[0]=v[1]; cenn2[1]=v[2]; cenn2[2]=v[3]; cenn2[3]=v[4];
        #pragma unroll
        for (int p = 0; p < 4; p++) {
            float vp = fmaxf(h3c[p], h3n[p]);
            float pool0 = fmaxf(h3m[p], vp);
            float s0v = cenc[p];
            if (s0v > 0.5f && s0v == pool0) EMIT(s0v, h0 + r, p);
            float pool1 = fmaxf(vp, h3n2[p]);
            float s1v = cenn[p];
            if (s1v > 0.5f && s1v == pool1) EMIT(s1v, h0 + r + 1, p);
        }
        #pragma unroll
        for (int q = 0; q < 4; q++) { h3m[q]=h3n[q]; h3c[q]=h3n2[q]; cenc[q]=cenn2[q]; }
    }
    __syncthreads();

    int c = scnt < SBUF_ ? scnt : SBUF_;
    for (int i = tid; i < c; i += 256) {
        int bu = (int)((unsigned)(sbuf[i] >> 48) & (NBUCK_-1));
        atomicAdd(&scntb[bu], 1u);
    }
    __syncthreads();
    if (tid < NBUCK_) {
        unsigned cnt = scntb[tid];
        if (cnt) sbase[tid] = atomicAdd(&g_bcnt[b][tid], cnt);
    }
    __syncthreads();
    for (int i = tid; i < c; i += 256) {
        unsigned long long key = sbuf[i];
        int bu = (int)((unsigned)(key >> 48) & (NBUCK_-1));
        unsigned pos = atomicAdd(&scur[bu], 1u) + sbase[bu];
        if (pos < CAPB_) g_bcand[b][bu][pos] = key;
    }
    #undef LOADROW
    #undef H3
    #undef EMIT
}

// ---------------- per-batch device barrier over PBLK_ blocks ----------------
__device__ __forceinline__ void batch_barrier(int b) {
    __syncthreads();
    if (threadIdx.x == 0) {
        __threadfence();
        unsigned gen = atomicAdd(&g_bargen[b], 0u);
        unsigned t = atomicAdd(&g_barcnt[b], 1u);
        if (t == PBLK_ - 1u) {
            g_barcnt[b] = 0u;
            __threadfence();
            atomicAdd(&g_bargen[b], 1u);
        } else {
            while (atomicAdd(&g_bargen[b], 0u) == gen) __nanosleep(64);
        }
    }
    __syncthreads();
}

// ---------------- K2: fused post-processing, grid (PBLK_, B_) x 256 ----------------
struct SA { unsigned sfx[NBIN_]; unsigned sbcnt[NBUCK_]; };
struct SB { unsigned long long skey[SPAN_]; };
struct SC { unsigned scell[NCELL_]; unsigned wsum[8]; };
struct SE { unsigned edges[EMAX_]; unsigned char keep[K_]; };

__global__ void __launch_bounds__(256) k_post(
    const float* __restrict__ deltas, const float* __restrict__ sizes,
    const int* __restrict__ p_stride, const int* __restrict__ p_offy,
    const int* __restrict__ p_offx,
    float* __restrict__ out, int out_size)
{
    const int bx = blockIdx.x, b = blockIdx.y;
    const int tid = threadIdx.x;
    const int lane = tid & 31, wid = tid >> 5;
    __shared__ union { SA a; SB bb; SC c; SE e; } u;
    __shared__ int sB, sT, sM, slo, shi;

    // ================= phase A: selection (block 0 only) =================
    if (bx == 0) {
        // zero per-call state
        for (int i = tid; i < NCELL_; i += 256) g_cellcnt[b][i] = 0u;
        if (tid == 0) { g_ne[b] = 0; sT = 0; }
        #pragma unroll
        for (int k = 0; k < 8; k++) u.a.sfx[tid + k*256] = 0u;
        if (tid < NBUCK_) {
            unsigned cnt = g_bcnt[b][tid];
            u.a.sbcnt[tid] = cnt < CAPB_ ? cnt : CAPB_;
            g_bcnt[b][tid] = 0u;          // reset for next replay
        }
        __syncthreads();

        // coarse threshold bucket
        if (tid == 0) {
            unsigned acc = 0; int Bst = 0;
            for (int bu = NBUCK_-1; bu >= 0; bu--) {
                acc += u.a.sbcnt[bu];
                if (acc >= K_) { Bst = bu; break; }
            }
            sB = Bst;
        }
        __syncthreads();
        const int Bst = sB;

        // fine histogram of surviving buckets
        for (int bu = Bst; bu < NBUCK_; bu++) {
            int cnt = (int)u.a.sbcnt[bu];
            for (int i = tid; i < cnt; i += 256) {
                unsigned long long key = g_bcand[b][bu][i];
                atomicAdd(&u.a.sfx[(unsigned)(key >> 44) & (NBIN_-1)], 1u);
            }
        }
        __syncthreads();

        // inclusive suffix sums
        for (int off = 1; off < NBIN_; off <<= 1) {
            unsigned vv[8];
            #pragma unroll
            for (int k = 0; k < 8; k++) {
                int i = tid + k*256;
                vv[k] = u.a.sfx[i] + ((i + off < NBIN_) ? u.a.sfx[i + off] : 0u);
            }
            __syncthreads();
            #pragma unroll
            for (int k = 0; k < 8; k++) u.a.sfx[tid + k*256] = vv[k];
            __syncthreads();
        }

        // threshold bin T
        #pragma unroll
        for (int k = 0; k < 8; k++) {
            int i = tid + k*256;
            unsigned s = u.a.sfx[i];
            unsigned nx = (i + 1 < NBIN_) ? u.a.sfx[i+1] : 0u;
            if (s >= K_ && nx < K_) sT = i;
        }
        __syncthreads();
        const int T = sT;
        if (tid == 0) {
            unsigned M = u.a.sfx[T];
            g_m[b] = (int)(M < SURV_ ? M : SURV_);
        }

        // base/segend to gmem; convert sfx to scatter cursors
        unsigned nx[8];
        #pragma unroll
        for (int k = 0; k < 8; k++) {
            int i = tid + k*256;
            unsigned s = u.a.sfx[i];
            unsigned n = (i + 1 < NBIN_) ? u.a.sfx[i+1] : 0u;
            g_base[b][i] = n; g_segend[b][i] = s;
            nx[k] = n;
        }
        __syncthreads();
        #pragma unroll
        for (int k = 0; k < 8; k++) u.a.sfx[tid + k*256] = nx[k];
        __syncthreads();

        // compaction with shared cursors
        for (int bu = Bst; bu < NBUCK_; bu++) {
            int cnt = (int)u.a.sbcnt[bu];
            for (int i = tid; i < cnt; i += 256) {
                unsigned long long key = g_bcand[b][bu][i];
                int bin = (int)((unsigned)(key >> 44) & (NBIN_-1));
                if (bin >= T) {
                    unsigned pos = atomicAdd(&u.a.sfx[bin], 1u);
                    if (pos < SURV_) g_surv[b][pos] = key;
                }
            }
        }
        // zero topk
        for (int i = tid; i < K_; i += 256) g_topk[b][i] = 0ull;
    }
    batch_barrier(b);

    // ================= phase B: rank + decode + cell count (all 16 blocks) =================
    {
        const int M = __ldcg(&g_m[b]);
        const int p = bx * 256 + tid;
        if (bx * 256 < M) {
            if (tid == 0) { slo = SURV_; shi = 0; }
            __syncthreads();
            unsigned long long key = 0ull;
            int s0 = 0, e = 0;
            if (p < M) {
                key = __ldcg(&g_surv[b][p]);
                int bin = (int)((unsigned)(key >> 44) & (NBIN_-1));
                s0 = (int)__ldcg(&g_base[b][bin]);
                e  = (int)__ldcg(&g_segend[b][bin]);
                if (e > SURV_) e = SURV_;
                atomicMin(&slo, s0);
                atomicMax(&shi, e);
            }
            __syncthreads();
            const int lo = slo, hi = shi;
            const int span = hi - lo;
            int rank = s0;

            if (span <= SPAN_) {
                for (int i = tid; i < span; i += 256) u.bb.skey[i] = __ldcg(&g_surv[b][lo + i]);
                __syncthreads();
                if (p < M) {
                    const unsigned long long* seg = &u.bb.skey[s0 - lo];
                    const int n = e - s0;
                    int c0 = 0, c1 = 0, c2 = 0, c3 = 0;
                    int m = 0;
                    for (; m + 4 <= n; m += 4) {
                        c0 += (seg[m]   > key);
                        c1 += (seg[m+1] > key);
                        c2 += (seg[m+2] > key);
                        c3 += (seg[m+3] > key);
                    }
                    for (; m < n; m++) c0 += (seg[m] > key);
                    rank += c0 + c1 + c2 + c3;
                }
            } else if (p < M) {
                int c0 = 0, c1 = 0, c2 = 0, c3 = 0;
                int m = s0;
                for (; m + 4 <= e; m += 4) {
                    c0 += (__ldcg(&g_surv[b][m])   > key);
                    c1 += (__ldcg(&g_surv[b][m+1]) > key);
                    c2 += (__ldcg(&g_surv[b][m+2]) > key);
                    c3 += (__ldcg(&g_surv[b][m+3]) > key);
                }
                for (; m < e; m++) c0 += (__ldcg(&g_surv[b][m]) > key);
                rank += c0 + c1 + c2 + c3;
            }

            if (p < M && rank < K_) {
                g_topk[b][rank] = key;
                const int stride = *p_stride, offy = *p_offy, offx = *p_offx;
                unsigned idx = ~(unsigned)key;
                int iw = (int)(idx & (W_-1)), ih = (int)(idx >> 10);
                float dx = deltas[((size_t)b*2 + 0)*HW_ + idx];
                float dy = deltas[((size_t)b*2 + 1)*HW_ + idx];
                float sx = sizes [((size_t)b*2 + 0)*HW_ + idx];
                float sy = sizes [((size_t)b*2 + 1)*HW_ + idx];
                float cx = (float)(iw*stride + offx) + dx;
                float cy = (float)(ih*stride + offy) + dy;
                float4 box;
                box.x = cx - sx*0.5f; box.y = cy - sy*0.5f;
                box.z = cx + sx*0.5f; box.w = cy + sy*0.5f;
                g_box[b][rank] = box;
                int ccx = min(31, max(0, (int)floorf((box.x+box.z)*0.5f*CELL_INV)));
                int ccy = min(31, max(0, (int)floorf((box.y+box.w)*0.5f*CELL_INV)));
                unsigned short cell = (unsigned short)(ccy*32 + ccx);
                g_cellof[b][rank] = cell;
                atomicAdd(&g_cellcnt[b][cell], 1u);
            }
        }
    }
    batch_barrier(b);

    // ================= phase C: cell scan + scatter (block 0) =================
    if (bx == 0) {
        unsigned c4[4];
        #pragma unroll
        for (int k = 0; k < 4; k++) c4[k] = __ldcg(&g_cellcnt[b][tid*4 + k]);
        unsigned tot = c4[0] + c4[1] + c4[2] + c4[3];
        unsigned x = tot;
        for (int o = 1; o < 32; o <<= 1) {
            unsigned y = __shfl_up_sync(0xffffffffu, x, o);
            if (lane >= o) x += y;
        }
        if (lane == 31) u.c.wsum[wid] = x;
        __syncthreads();
        if (tid == 0) {
            unsigned acc = 0;
            #pragma unroll
            for (int w = 0; w < 8; w++) { unsigned t2 = u.c.wsum[w]; u.c.wsum[w] = acc; acc += t2; }
        }
        __syncthreads();
        unsigned excl = u.c.wsum[wid] + (x - tot);
        unsigned run = excl;
        #pragma unroll
        for (int k = 0; k < 4; k++) {
            int cell = tid*4 + k;
            g_cstart[b][cell] = (unsigned short)run;
            u.c.scell[cell] = run;
            run += c4[k];
        }
        if (tid == 255) g_cstart[b][NCELL_] = (unsigned short)run;
        __syncthreads();

        for (int t = tid; t < K_; t += 256) {
            if (__ldcg(&g_topk[b][t]) != 0ull) {
                unsigned short cell = __ldcg(&g_cellof[b][t]);
                unsigned p = atomicAdd(&u.c.scell[cell], 1u);
                g_list[b][p] = (unsigned short)t;
            }
        }
    }
    batch_barrier(b);

    // ================= phase D: sparse edges (blocks 0..7) =================
    if (bx < 8) {
        const int t = bx * 256 + tid;
        unsigned long long key = __ldcg(&g_topk[b][t]);
        if (key != 0ull) {
            float4 bj = __ldcg(&g_box[b][t]);
            float aj = (bj.z - bj.x) * (bj.w - bj.y);
            int cc = __ldcg(&g_cellof[b][t]);
            int ccx = cc & 31, ccy = cc >> 5;
            int gy0 = max(ccy-1,0), gy1 = min(ccy+1,31);
            int gx0 = max(ccx-1,0), gx1 = min(ccx+1,31);
            for (int gy = gy0; gy <= gy1; gy++)
            for (int gx = gx0; gx <= gx1; gx++) {
                int c = gy*32 + gx;
                int ps = __ldcg(&g_cstart[b][c]);
                int pe = __ldcg(&g_cstart[b][c+1]);
                for (int p = ps; p < pe; p++) {
                    int i = __ldcg(&g_list[b][p]);
                    if (i >= t) continue;
                    float4 bi = __ldcg(&g_box[b][i]);
                    float xx1 = fmaxf(bi.x, bj.x);
                    float yy1 = fmaxf(bi.y, bj.y);
                    float xx2 = fminf(bi.z, bj.z);
                    float yy2 = fminf(bi.w, bj.w);
                    float iw2 = xx2 - xx1, ih2 = yy2 - yy1;
                    if (iw2 <= 0.f || ih2 <= 0.f) continue;
                    float inter = iw2 * ih2;
                    float ai = (bi.z - bi.x) * (bi.w - bi.y);
                    float iou = inter / (ai + aj - inter + 1e-12f);
                    if (iou > 0.5f) {
                        int e = atomicAdd(&g_ne[b], 1);
                        if (e < EMAX_) g_edges[b][e] = ((unsigned)t << 16) | (unsigned)i;
                    }
                }
            }
        }
    }
    batch_barrier(b);

    // ================= phase E: greedy resolve + outputs (block 0) =================
    if (bx == 0) {
        int E = __ldcg(&g_ne[b]); if (E > EMAX_) E = EMAX_;
        for (int i = tid; i < E; i += 256) u.e.edges[i] = __ldcg(&g_edges[b][i]);
        for (int t = tid; t < K_; t += 256)
            u.e.keep[t] = (__ldcg(&g_topk[b][t]) != 0ull) ? 1 : 0;
        __syncthreads();

        if (tid == 0) {
            for (int a = 1; a < E; a++) {
                unsigned v = u.e.edges[a]; int q = a - 1;
                while (q >= 0 && u.e.edges[q] > v) { u.e.edges[q+1] = u.e.edges[q]; q--; }
                u.e.edges[q+1] = v;
            }
            for (int e = 0; e < E; e++) {
                int j = (int)(u.e.edges[e] >> 16), i = (int)(u.e.edges[e] & 0xffffu);
                if (u.e.keep[i]) u.e.keep[j] = 0;
            }
        }
        __syncthreads();

        const int so = 0, bo = B_*K_, ko = B_*K_*5;
        for (int t = tid; t < K_; t += 256) {
            unsigned long long key = __ldcg(&g_topk[b][t]);
            float val = __uint_as_float((unsigned)(key >> 32));
            bool kp = u.e.keep[t] != 0;
            float4 box = __ldcg(&g_box[b][t]);
            int g = b*K_ + t;
            if (so + g < out_size) out[so + g] = kp ? val : 0.f;
            if (bo + g*4 + 3 < out_size) {
                float4 bxo;
                bxo.x = kp ? box.x : 0.f;
                bxo.y = kp ? box.y : 0.f;
                bxo.z = kp ? box.z : 0.f;
                bxo.w = kp ? box.w : 0.f;
                *reinterpret_cast<float4*>(out + bo + g*4) = bxo;
            }
            if (ko + g < out_size) out[ko + g] = kp ? 1.f : 0.f;
        }
    }
}

// ---------------- launch ----------------
extern "C" void kernel_launch(void* const* d_in, const int* in_sizes, int n_in,
                              void* d_out, int out_size) {
    (void)in_sizes; (void)n_in;
    const float* scores = (const float*)d_in[0];
    const float* deltas = (const float*)d_in[1];
    const float* sizes  = (const float*)d_in[2];
    const int* p_stride = (const int*)d_in[3];
    const int* p_offy   = (const int*)d_in[4];
    const int* p_offx   = (const int*)d_in[5];

    dim3 g1(H_ / RPB_, B_);
    k_cand<<<g1, 256>>>(scores);
    dim3 g2(PBLK_, B_);
    k_post<<<g2, 256>>>(deltas, sizes, p_stride, p_offy, p_offx,
                        (float*)d_out, out_size);
}

// round 16
// speedup vs baseline: 1.5554x; 1.5554x over previous
#include <cuda_runtime.h>
#include <cstdint>

#define B_ 8
#define H_ 1024
#define W_ 1024
#define HW_ (H_*W_)
#define K_ 2048
#define SURV_ 4096
#define NBIN_ 2048
#define NBUCK_ 128
#define CAPB_ 8192
#define NCELL_ 1024   /* 32x32 grid */
#define CELL_INV (1.0f/256.0f)
#define EMAX_ 512
#define RPB_ 16       /* rows per block in k_cand */
#define SBUF_ 2048    /* per-block candidate staging */
#define PBLK_ 8       /* post blocks per batch */
#define KPB_ 512      /* rank keys per block = SURV_/PBLK_ */
#define SPAN_ 2048    /* rank shared staging capacity (keys) */

// ---------------- scratch (static device memory only) ----------------
__device__ unsigned long long g_bcand[B_][NBUCK_][CAPB_];
__device__ unsigned g_bcnt[B_][NBUCK_];      // zeroed by k_post each call
__device__ unsigned g_base[B_][NBIN_];
__device__ unsigned g_segend[B_][NBIN_];
__device__ unsigned long long g_surv[B_][SURV_];
__device__ int g_m[B_];
__device__ unsigned long long g_topk[B_][K_];
__device__ float4 g_box[B_][K_];
__device__ unsigned g_cellcnt[B_][NCELL_];
__device__ unsigned short g_cellof[B_][K_];
__device__ unsigned short g_cstart[B_][NCELL_ + 1];
__device__ unsigned short g_list[B_][K_];
__device__ unsigned g_edges[B_][EMAX_];
__device__ int g_ne[B_];
__device__ unsigned g_barcnt[B_];
__device__ unsigned g_bargen[B_];

// ---------------- K1: local-max candidates (unchanged, proven) ----------------
__global__ void __launch_bounds__(256) k_cand(const float* __restrict__ sc) {
    const int b = blockIdx.y, h0 = blockIdx.x * RPB_;
    const int tid = threadIdx.x;
    const int w0 = tid * 4;
    const int lane = tid & 31;
    const float NI = -__int_as_float(0x7f800000);

    __shared__ int scnt;
    __shared__ unsigned long long sbuf[SBUF_];
    __shared__ unsigned scntb[NBUCK_];
    __shared__ unsigned sbase[NBUCK_];
    __shared__ unsigned scur[NBUCK_];
    if (tid < NBUCK_) { scntb[tid] = 0u; scur[tid] = 0u; }
    if (tid == 0) scnt = 0;
    __syncthreads();

    float v[6];
    float h3m[4], h3c[4], h3n[4], h3n2[4];
    float cenc[4], cenn[4], cenn2[4];

    #define LOADROW(hh) do {                                                \
        int _h = (hh);                                                      \
        if ((unsigned)_h >= (unsigned)H_) {                                 \
            v[0]=NI; v[1]=NI; v[2]=NI; v[3]=NI; v[4]=NI; v[5]=NI;           \
        } else {                                                            \
            const float* _r = sc + ((size_t)b * H_ + _h) * W_;              \
            float4 _m = *reinterpret_cast<const float4*>(_r + w0);          \
            float _lw = __shfl_up_sync(0xffffffffu, _m.w, 1);               \
            float _rx = __shfl_down_sync(0xffffffffu, _m.x, 1);             \
            v[1]=_m.x; v[2]=_m.y; v[3]=_m.z; v[4]=_m.w;                     \
            v[0] = lane        ? _lw : ((w0 > 0)      ? _r[w0-1] : NI);     \
            v[5] = (lane != 31)? _rx : ((w0 + 4 < W_) ? _r[w0+4] : NI);     \
        }                                                                   \
    } while (0)
    #define H3(d) do {                                                      \
        float _q0 = fmaxf(v[0], v[1]);                                      \
        float _q2 = fmaxf(v[2], v[3]);                                      \
        float _q4 = fmaxf(v[4], v[5]);                                      \
        d[0] = fmaxf(_q0, v[2]);                                            \
        d[1] = fmaxf(v[1], _q2);                                            \
        d[2] = fmaxf(_q2, v[4]);                                            \
        d[3] = fmaxf(v[3], _q4);                                            \
    } while (0)
    #define EMIT(s_, hh_, p_) do {                                          \
        int _pos = atomicAdd(&scnt, 1);                                     \
        if (_pos < SBUF_) {                                                 \
            unsigned _idx = (unsigned)((hh_) * W_ + w0 + (p_));             \
            unsigned _sb = __float_as_uint(s_);                             \
            sbuf[_pos] = ((unsigned long long)_sb << 32) | (unsigned)(~_idx);\
        }                                                                   \
    } while (0)

    LOADROW(h0 - 1); H3(h3m);
    LOADROW(h0);     H3(h3c); cenc[0]=v[1]; cenc[1]=v[2]; cenc[2]=v[3]; cenc[3]=v[4];

    #pragma unroll
    for (int r = 0; r < RPB_; r += 2) {
        LOADROW(h0 + r + 1); H3(h3n);  cenn[0]=v[1];  cenn[1]=v[2];  cenn[2]=v[3];  cenn[3]=v[4];
        LOADROW(h0 + r + 2); H3(h3n2); cenn2[0]=v[1]; cenn2[1]=v[2]; cenn2[2]=v[3]; cenn2[3]=v[4];
        #pragma unroll
        for (int p = 0; p < 4; p++) {
            float vp = fmaxf(h3c[p], h3n[p]);
            float pool0 = fmaxf(h3m[p], vp);
            float s0v = cenc[p];
            if (s0v > 0.5f && s0v == pool0) EMIT(s0v, h0 + r, p);
            float pool1 = fmaxf(vp, h3n2[p]);
            float s1v = cenn[p];
            if (s1v > 0.5f && s1v == pool1) EMIT(s1v, h0 + r + 1, p);
        }
        #pragma unroll
        for (int q = 0; q < 4; q++) { h3m[q]=h3n[q]; h3c[q]=h3n2[q]; cenc[q]=cenn2[q]; }
    }
    __syncthreads();

    int c = scnt < SBUF_ ? scnt : SBUF_;
    for (int i = tid; i < c; i += 256) {
        int bu = (int)((unsigned)(sbuf[i] >> 48) & (NBUCK_-1));
        atomicAdd(&scntb[bu], 1u);
    }
    __syncthreads();
    if (tid < NBUCK_) {
        unsigned cnt = scntb[tid];
        if (cnt) sbase[tid] = atomicAdd(&g_bcnt[b][tid], cnt);
    }
    __syncthreads();
    for (int i = tid; i < c; i += 256) {
        unsigned long long key = sbuf[i];
        int bu = (int)((unsigned)(key >> 48) & (NBUCK_-1));
        unsigned pos = atomicAdd(&scur[bu], 1u) + sbase[bu];
        if (pos < CAPB_) g_bcand[b][bu][pos] = key;
    }
    #undef LOADROW
    #undef H3
    #undef EMIT
}

// ---------------- per-batch device barrier over PBLK_ blocks ----------------
__device__ __forceinline__ void batch_barrier(int b) {
    __syncthreads();
    if (threadIdx.x == 0) {
        __threadfence();
        unsigned gen = atomicAdd(&g_bargen[b], 0u);
        unsigned t = atomicAdd(&g_barcnt[b], 1u);
        if (t == PBLK_ - 1u) {
            g_barcnt[b] = 0u;
            __threadfence();
            atomicAdd(&g_bargen[b], 1u);
        } else {
            while (atomicAdd(&g_bargen[b], 0u) == gen) __nanosleep(32);
        }
    }
    __syncthreads();
}

// ---------------- K2: fused post, grid (PBLK_, B_) x 1024 ----------------
struct SA { unsigned sfx[NBIN_]; unsigned sbcnt[NBUCK_]; };
struct SB { unsigned long long skey[SPAN_]; };
struct SC { unsigned scell[NCELL_]; unsigned wsum[32]; };
struct SD { float4 box[K_]; unsigned short cs[NCELL_ + 2]; unsigned short lst[K_]; };
struct SE { unsigned edges[EMAX_]; unsigned char keep[K_]; };

__global__ void __launch_bounds__(1024) k_post(
    const float* __restrict__ deltas, const float* __restrict__ sizes,
    const int* __restrict__ p_stride, const int* __restrict__ p_offy,
    const int* __restrict__ p_offx,
    float* __restrict__ out, int out_size)
{
    const int bx = blockIdx.x, b = blockIdx.y;
    const int tid = threadIdx.x;
    const int lane = tid & 31, wid = tid >> 5;
    __shared__ union { SA a; SB bb; SC c; SD d; SE e; } u;
    __shared__ int sB, sT, slo, shi;

    // ================= phase A: selection (block 0, 1024 thr) =================
    if (bx == 0) {
        g_cellcnt[b][tid] = 0u;
        if (tid == 0) { g_ne[b] = 0; sT = 0; }
        u.a.sfx[tid] = 0u; u.a.sfx[tid + 1024] = 0u;
        if (tid < NBUCK_) {
            unsigned cnt = g_bcnt[b][tid];
            u.a.sbcnt[tid] = cnt < CAPB_ ? cnt : CAPB_;
            g_bcnt[b][tid] = 0u;
        }
        for (int i = tid; i < K_; i += 1024) g_topk[b][i] = 0ull;
        __syncthreads();

        if (tid == 0) {
            unsigned acc = 0; int Bst = 0;
            for (int bu = NBUCK_-1; bu >= 0; bu--) {
                acc += u.a.sbcnt[bu];
                if (acc >= K_) { Bst = bu; break; }
            }
            sB = Bst;
        }
        __syncthreads();
        const int Bst = sB;

        for (int bu = Bst; bu < NBUCK_; bu++) {
            int cnt = (int)u.a.sbcnt[bu];
            for (int i = tid; i < cnt; i += 1024) {
                unsigned long long key = g_bcand[b][bu][i];
                atomicAdd(&u.a.sfx[(unsigned)(key >> 44) & (NBIN_-1)], 1u);
            }
        }
        __syncthreads();

        for (int off = 1; off < NBIN_; off <<= 1) {
            unsigned v0 = u.a.sfx[tid]      + ((tid + off        < NBIN_) ? u.a.sfx[tid + off]        : 0u);
            unsigned v1 = u.a.sfx[tid+1024] + ((tid + 1024 + off < NBIN_) ? u.a.sfx[tid + 1024 + off] : 0u);
            __syncthreads();
            u.a.sfx[tid] = v0; u.a.sfx[tid + 1024] = v1;
            __syncthreads();
        }

        for (int i = tid; i < NBIN_; i += 1024) {
            unsigned s = u.a.sfx[i];
            unsigned nx = (i + 1 < NBIN_) ? u.a.sfx[i+1] : 0u;
            if (s >= K_ && nx < K_) sT = i;
        }
        __syncthreads();
        const int T = sT;
        if (tid == 0) {
            unsigned M = u.a.sfx[T];
            g_m[b] = (int)(M < SURV_ ? M : SURV_);
        }

        unsigned base0, base1;
        {
            unsigned s0 = u.a.sfx[tid],      n0 = (tid + 1 < NBIN_)        ? u.a.sfx[tid+1]      : 0u;
            unsigned s1 = u.a.sfx[tid+1024], n1 = (tid + 1024 + 1 < NBIN_) ? u.a.sfx[tid+1024+1] : 0u;
            g_base[b][tid] = n0;        g_segend[b][tid] = s0;
            g_base[b][tid+1024] = n1;   g_segend[b][tid+1024] = s1;
            base0 = n0; base1 = n1;
        }
        __syncthreads();
        u.a.sfx[tid] = base0; u.a.sfx[tid + 1024] = base1;
        __syncthreads();

        for (int bu = Bst; bu < NBUCK_; bu++) {
            int cnt = (int)u.a.sbcnt[bu];
            for (int i = tid; i < cnt; i += 1024) {
                unsigned long long key = g_bcand[b][bu][i];
                int bin = (int)((unsigned)(key >> 44) & (NBIN_-1));
                if (bin >= T) {
                    unsigned pos = atomicAdd(&u.a.sfx[bin], 1u);
                    if (pos < SURV_) g_surv[b][pos] = key;
                }
            }
        }
    }
    batch_barrier(b);

    // ================= phase B: rank + decode + cell count (8 blocks x 1024) =================
    {
        const int M = __ldcg(&g_m[b]);
        const int base = bx * KPB_;
        if (base < M) {
            if (tid == 0) { slo = SURV_; shi = 0; }
            __syncthreads();
            unsigned long long key = 0ull;
            int s0 = 0, e = 0;
            const int p = base + tid;   // tid < KPB_ handles a key
            const bool active = (tid < KPB_) && (p < M);
            if (active) {
                key = __ldcg(&g_surv[b][p]);
                int bin = (int)((unsigned)(key >> 44) & (NBIN_-1));
                s0 = (int)__ldcg(&g_base[b][bin]);
                e  = (int)__ldcg(&g_segend[b][bin]);
                if (e > SURV_) e = SURV_;
                atomicMin(&slo, s0);
                atomicMax(&shi, e);
            }
            __syncthreads();
            const int lo = slo, hi = shi;
            const int span = hi - lo;
            int rank = s0;

            if (span <= SPAN_) {
                for (int i = tid; i < span; i += 1024) u.bb.skey[i] = __ldcg(&g_surv[b][lo + i]);
                __syncthreads();
                if (active) {
                    const unsigned long long* seg = &u.bb.skey[s0 - lo];
                    const int n = e - s0;
                    int c0 = 0, c1 = 0, c2 = 0, c3 = 0;
                    int m = 0;
                    for (; m + 4 <= n; m += 4) {
                        c0 += (seg[m]   > key);
                        c1 += (seg[m+1] > key);
                        c2 += (seg[m+2] > key);
                        c3 += (seg[m+3] > key);
                    }
                    for (; m < n; m++) c0 += (seg[m] > key);
                    rank += c0 + c1 + c2 + c3;
                }
            } else if (active) {
                int c0 = 0, c1 = 0, c2 = 0, c3 = 0;
                int m = s0;
                for (; m + 4 <= e; m += 4) {
                    c0 += (__ldcg(&g_surv[b][m])   > key);
                    c1 += (__ldcg(&g_surv[b][m+1]) > key);
                    c2 += (__ldcg(&g_surv[b][m+2]) > key);
                    c3 += (__ldcg(&g_surv[b][m+3]) > key);
                }
                for (; m < e; m++) c0 += (__ldcg(&g_surv[b][m]) > key);
                rank += c0 + c1 + c2 + c3;
            }

            if (active && rank < K_) {
                g_topk[b][rank] = key;
                const int stride = *p_stride, offy = *p_offy, offx = *p_offx;
                unsigned idx = ~(unsigned)key;
                int iw = (int)(idx & (W_-1)), ih = (int)(idx >> 10);
                float dx = deltas[((size_t)b*2 + 0)*HW_ + idx];
                float dy = deltas[((size_t)b*2 + 1)*HW_ + idx];
                float sx = sizes [((size_t)b*2 + 0)*HW_ + idx];
                float sy = sizes [((size_t)b*2 + 1)*HW_ + idx];
                float cx = (float)(iw*stride + offx) + dx;
                float cy = (float)(ih*stride + offy) + dy;
                float4 box;
                box.x = cx - sx*0.5f; box.y = cy - sy*0.5f;
                box.z = cx + sx*0.5f; box.w = cy + sy*0.5f;
                g_box[b][rank] = box;
                int ccx = min(31, max(0, (int)floorf((box.x+box.z)*0.5f*CELL_INV)));
                int ccy = min(31, max(0, (int)floorf((box.y+box.w)*0.5f*CELL_INV)));
                unsigned short cell = (unsigned short)(ccy*32 + ccx);
                g_cellof[b][rank] = cell;
                atomicAdd(&g_cellcnt[b][cell], 1u);
            }
        }
    }
    batch_barrier(b);

    // ================= phase C: cell scan + scatter (block 0, 1024 thr) =================
    if (bx == 0) {
        unsigned orig = __ldcg(&g_cellcnt[b][tid]);
        unsigned x = orig;
        for (int o = 1; o < 32; o <<= 1) {
            unsigned y = __shfl_up_sync(0xffffffffu, x, o);
            if (lane >= o) x += y;
        }
        if (lane == 31) u.c.wsum[wid] = x;
        __syncthreads();
        if (wid == 0) {
            unsigned s2 = u.c.wsum[lane];
            for (int o = 1; o < 32; o <<= 1) {
                unsigned y = __shfl_up_sync(0xffffffffu, s2, o);
                if (lane >= o) s2 += y;
            }
            u.c.wsum[lane] = s2;
        }
        __syncthreads();
        unsigned incl = x + (wid > 0 ? u.c.wsum[wid-1] : 0u);
        unsigned excl = incl - orig;
        g_cstart[b][tid] = (unsigned short)excl;
        if (tid == NCELL_-1) g_cstart[b][NCELL_] = (unsigned short)incl;
        __syncthreads();          // wsum reads done before scell overwrite (union-safe: different fields)
        u.c.scell[tid] = excl;
        __syncthreads();

        #pragma unroll
        for (int k = 0; k < 2; k++) {
            int t = tid + k * 1024;
            if (__ldcg(&g_topk[b][t]) != 0ull) {
                unsigned short cell = __ldcg(&g_cellof[b][t]);
                unsigned p = atomicAdd(&u.c.scell[cell], 1u);
                g_list[b][p] = (unsigned short)t;
            }
        }
    }
    batch_barrier(b);

    // ================= phase D: edges from SHARED-staged structures (8 blocks) =================
    {
        for (int i = tid; i < K_; i += 1024) u.d.box[i] = __ldcg(&g_box[b][i]);
        for (int i = tid; i < NCELL_ + 1; i += 1024) u.d.cs[i] = __ldcg(&g_cstart[b][i]);
        #pragma unroll
        for (int k = 0; k < 2; k++) u.d.lst[tid + k*1024] = __ldcg(&g_list[b][tid + k*1024]);
        __syncthreads();

        const int grp = tid >> 8;               // 0..3 (group 3 idle)
        const int t = bx * 256 + (tid & 255);
        if (grp < 3 && __ldcg(&g_topk[b][t]) != 0ull) {
            float4 bj = u.d.box[t];
            float aj = (bj.z - bj.x) * (bj.w - bj.y);
            int cc = __ldcg(&g_cellof[b][t]);
            int ccx = cc & 31, ccy = cc >> 5;
            int gy = ccy - 1 + grp;
            if (gy >= 0 && gy <= 31) {
                int gx0 = max(ccx-1,0), gx1 = min(ccx+1,31);
                for (int gx = gx0; gx <= gx1; gx++) {
                    int c = gy*32 + gx;
                    int ps = u.d.cs[c], pe = u.d.cs[c+1];
                    for (int p = ps; p < pe; p++) {
                        int i = u.d.lst[p];
                        if (i >= t) continue;
                        float4 bi = u.d.box[i];
                        float xx1 = fmaxf(bi.x, bj.x);
                        float yy1 = fmaxf(bi.y, bj.y);
                        float xx2 = fminf(bi.z, bj.z);
                        float yy2 = fminf(bi.w, bj.w);
                        float iw2 = xx2 - xx1, ih2 = yy2 - yy1;
                        if (iw2 <= 0.f || ih2 <= 0.f) continue;
                        float inter = iw2 * ih2;
                        float ai = (bi.z - bi.x) * (bi.w - bi.y);
                        float iou = inter / (ai + aj - inter + 1e-12f);
                        if (iou > 0.5f) {
                            int e = atomicAdd(&g_ne[b], 1);
                            if (e < EMAX_) g_edges[b][e] = ((unsigned)t << 16) | (unsigned)i;
                        }
                    }
                }
            }
        }
    }
    batch_barrier(b);

    // ================= phase E: greedy resolve + outputs (block 0, 1024 thr) =================
    if (bx == 0) {
        int E = __ldcg(&g_ne[b]); if (E > EMAX_) E = EMAX_;
        for (int i = tid; i < E; i += 1024) u.e.edges[i] = __ldcg(&g_edges[b][i]);
        #pragma unroll
        for (int k = 0; k < 2; k++) {
            int t = tid + k * 1024;
            u.e.keep[t] = (__ldcg(&g_topk[b][t]) != 0ull) ? 1 : 0;
        }
        __syncthreads();

        if (tid == 0) {
            for (int a = 1; a < E; a++) {
                unsigned v = u.e.edges[a]; int q = a - 1;
                while (q >= 0 && u.e.edges[q] > v) { u.e.edges[q+1] = u.e.edges[q]; q--; }
                u.e.edges[q+1] = v;
            }
            for (int e = 0; e < E; e++) {
                int j = (int)(u.e.edges[e] >> 16), i = (int)(u.e.edges[e] & 0xffffu);
                if (u.e.keep[i]) u.e.keep[j] = 0;
            }
        }
        __syncthreads();

        const int so = 0, bo = B_*K_, ko = B_*K_*5;
        #pragma unroll
        for (int k = 0; k < 2; k++) {
            int t = tid + k * 1024;
            unsigned long long key = __ldcg(&g_topk[b][t]);
            float val = __uint_as_float((unsigned)(key >> 32));
            bool kp = u.e.keep[t] != 0;
            float4 box = __ldcg(&g_box[b][t]);
            int g = b*K_ + t;
            if (so + g < out_size) out[so + g] = kp ? val : 0.f;
            if (bo + g*4 + 3 < out_size) {
                float4 bxo;
                bxo.x = kp ? box.x : 0.f;
                bxo.y = kp ? box.y : 0.f;
                bxo.z = kp ? box.z : 0.f;
                bxo.w = kp ? box.w : 0.f;
                *reinterpret_cast<float4*>(out + bo + g*4) = bxo;
            }
            if (ko + g < out_size) out[ko + g] = kp ? 1.f : 0.f;
        }
    }
}

// ---------------- launch ----------------
extern "C" void kernel_launch(void* const* d_in, const int* in_sizes, int n_in,
                              void* d_out, int out_size) {
    (void)in_sizes; (void)n_in;
    const float* scores = (const float*)d_in[0];
    const float* deltas = (const float*)d_in[1];
    const float* sizes  = (const float*)d_in[2];
    const int* p_stride = (const int*)d_in[3];
    const int* p_offy   = (const int*)d_in[4];
    const int* p_offx   = (const int*)d_in[5];

    dim3 g1(H_ / RPB_, B_);
    k_cand<<<g1, 256>>>(scores);
    dim3 g2(PBLK_, B_);
    k_post<<<g2, 1024>>>(deltas, sizes, p_stride, p_offy, p_offx,
                         (float*)d_out, out_size);
}